// round 16
// baseline (speedup 1.0000x reference)
#include <cuda_runtime.h>
#include <cstdint>

// ---------------------------------------------------------------------------
// BinConv(3x3,pad1)+bias+ReLU+eval-BN via bit-packed XNOR + CSA-popcount.
//   conv = C0 - 2*S,  S = sum_{18 words} popc(xbits ^ wbits)
//   Balanced k=9 CSA tree: 18 XOR words -> 6 L1 CSAs -> {u0,u1}@1+{d0,d1}@2
//   (sum side) and c0..c5 -> CSA(c0,c1,c2)={v0}@2+{e0}@4 (carry side)
//   -> 9 popcounts (mufu 72) vs 36 LOP3 (alu 72): pipes balanced.
//   float(S) via 2^23 magic number (no I2F).
// 2-kernel DAG: k_prep (binx all imgs + binw fused as grid-z slice) -> k_main.
// No stream overlap (R9/R13/R14: always net-negative vs alu-saturated k_main).
// ---------------------------------------------------------------------------

#define N_IMG 16
#define HDIM 256
#define WDIM 256
#define HP 258
#define WP 258

// zero-initialized: padded borders stay 0
__device__ __align__(16) unsigned int g_xb[(size_t)N_IMG * HP * WP * 2];
__device__ __align__(16) unsigned int g_wb[64 * 20];   // [co][tap*2+word], pad 20
__device__ float g_C0p[3 * 64], g_ELp[3 * 64], g_ERp[3 * 64];
__device__ float g_scale[64], g_shift[64];

// ---------------------------------------------------------------------------
// Fused prep. grid (4,256,17), block 256.
//   z < 16            : binarize+pack x rows (image z)
//   z == 16, x==0,y<64: pack weights + fold constants (cout = blockIdx.y)
// ---------------------------------------------------------------------------
__global__ void k_prep(const float* __restrict__ x, const float* __restrict__ w,
                       const float* __restrict__ b, const float* __restrict__ gamma,
                       const float* __restrict__ beta, const float* __restrict__ mean,
                       const float* __restrict__ var) {
    const int tid = threadIdx.x;

    if (blockIdx.z < N_IMG) {
        // ---------------- binx ----------------
        __shared__ unsigned short s16[64][4];
        const int n = blockIdx.z, h = blockIdx.y, w0 = blockIdx.x * 64;
        const int ww_ = tid & 63, cb = tid >> 6;
        const float* xp =
            x + (((size_t)n * 64 + cb * 16) * HDIM + h) * WDIM + w0 + ww_;
        unsigned int m = 0;
#pragma unroll
        for (int ci = 0; ci < 16; ci++) {
            float v = xp[(size_t)ci * (HDIM * WDIM)];
            m |= (v >= 0.0f ? 1u : 0u) << ci;
        }
        s16[ww_][cb] = (unsigned short)m;
        __syncthreads();
        if (tid < 128) {
            int wq = tid >> 1, word = tid & 1;
            unsigned int v = (unsigned int)s16[wq][2 * word] |
                             ((unsigned int)s16[wq][2 * word + 1] << 16);
            g_xb[(((size_t)n * HP + h + 1) * WP + (w0 + 1 + wq)) * 2 + word] = v;
        }
        return;
    }

    // ---------------- binw (64 blocks: x==0, y<64) ----------------
    if (blockIdx.x != 0 || blockIdx.y >= 64 || tid >= 64) return;
    __shared__ unsigned int sw[18];
    const int co = blockIdx.y, c = tid;
    const int lane = c & 31, warp = c >> 5;
#pragma unroll
    for (int tap = 0; tap < 9; tap++) {
        float wv = w[((size_t)co * 64 + c) * 9 + tap];
        unsigned int bal = __ballot_sync(0xffffffffu, wv >= 0.0f);
        if (lane == 0) sw[tap * 2 + warp] = bal;
    }
    __syncthreads();
    if (c < 18) g_wb[co * 20 + c] = sw[c];
    if (c == 0) {
        int tp[9];
        for (int t = 0; t < 9; t++)
            tp[t] = __popc(sw[t * 2]) + __popc(sw[t * 2 + 1]);
        float corr[3][3];
        for (int hp = 0; hp < 3; hp++)
            for (int lr = 0; lr < 3; lr++) {
                float s = 0.0f;
                for (int dy = 0; dy < 3; dy++)
                    for (int dx = 0; dx < 3; dx++) {
                        bool cut = (hp == 1 && dy == 0) || (hp == 2 && dy == 2) ||
                                   (lr == 1 && dx == 0) || (lr == 2 && dx == 2);
                        if (cut) s += 64.0f - 2.0f * (float)tp[dy * 3 + dx];
                    }
                corr[hp][lr] = s;
            }
        float bias = b[co];
        for (int hp = 0; hp < 3; hp++) {
            g_C0p[hp * 64 + co] = bias + 576.0f - corr[hp][0];
            g_ELp[hp * 64 + co] = corr[hp][0] - corr[hp][1];
            g_ERp[hp * 64 + co] = corr[hp][0] - corr[hp][2];
        }
        float inv = gamma[co] * rsqrtf(var[co] + 1e-5f);
        g_scale[co] = inv;
        g_shift[co] = beta[co] - mean[co] * inv;
    }
}

// ---------------------------------------------------------------------------
// Main: XNOR + CSA-popcount. CTA = 1 row (256 px) x 64 couts, 512 threads.
// thread = 1 px x 32 couts. grid (1,256,16).
// ---------------------------------------------------------------------------
#define CSA(s, cy, a, b, c)                          \
    {                                                \
        unsigned int _a = (a), _b = (b), _c = (c);   \
        (s) = _a ^ _b ^ _c;                          \
        (cy) = (_a & _b) | (_a & _c) | (_b & _c);    \
    }
#define MAJ(a, b, c) (((a) & (b)) | ((a) & (c)) | ((b) & (c)))

__global__ void __launch_bounds__(512, 2) k_main(float* __restrict__ out) {
    __shared__ uint2 s_x[3][260];
    __shared__ unsigned int s_w[64 * 20];
    __shared__ float sC0I[64], sC0L[64], sC0R[64], sSC[64], sSH[64];

    const int tid = threadIdx.x;
    const int n = blockIdx.z, h = blockIdx.y;
    const int hp = (h == 0) ? 1 : ((h == HDIM - 1) ? 2 : 0);

    {
        const uint2* xg = (const uint2*)g_xb + ((size_t)n * HP + h) * WP;
        for (int t = tid; t < 774; t += 512) {
            int dy = t / 258, i = t - dy * 258;
            s_x[dy][i] = xg[(size_t)dy * WP + i];
        }
    }
    for (int t = tid; t < 1280; t += 512) s_w[t] = g_wb[t];
    if (tid < 64) {
        float c0 = g_C0p[hp * 64 + tid];
        sC0I[tid] = c0;
        sC0L[tid] = c0 + g_ELp[hp * 64 + tid];
        sC0R[tid] = c0 + g_ERp[hp * 64 + tid];
        sSC[tid] = g_scale[tid];
        sSH[tid] = g_shift[tid];
    }
    __syncthreads();

    const int px = tid & 255, g = tid >> 8;

    uint2 xr0a = s_x[0][px], xr0b = s_x[0][px + 1], xr0c = s_x[0][px + 2];
    uint2 xr1a = s_x[1][px], xr1b = s_x[1][px + 1], xr1c = s_x[1][px + 2];
    uint2 xr2a = s_x[2][px], xr2b = s_x[2][px + 1], xr2c = s_x[2][px + 2];

    const float* c0v = (px == 0) ? sC0L : ((px == 255) ? sC0R : sC0I);
    const unsigned int* wb = s_w + g * 32 * 20;
    float* op = out + (((size_t)n * 64 + g * 32) * HDIM + h) * WDIM + px;

#pragma unroll 4
    for (int c = 0; c < 32; c++) {
        const uint4* w4 = (const uint4*)(wb + c * 20);
        uint4 wq0 = w4[0], wq1 = w4[1], wq2 = w4[2], wq3 = w4[3];
        uint2 wq4 = *(const uint2*)(w4 + 4);
        unsigned int t0 = xr0a.x ^ wq0.x, t1 = xr0a.y ^ wq0.y;
        unsigned int t2 = xr0b.x ^ wq0.z, t3 = xr0b.y ^ wq0.w;
        unsigned int t4 = xr0c.x ^ wq1.x, t5 = xr0c.y ^ wq1.y;
        unsigned int t6 = xr1a.x ^ wq1.z, t7 = xr1a.y ^ wq1.w;
        unsigned int t8 = xr1b.x ^ wq2.x, t9 = xr1b.y ^ wq2.y;
        unsigned int t10 = xr1c.x ^ wq2.z, t11 = xr1c.y ^ wq2.w;
        unsigned int t12 = xr2a.x ^ wq3.x, t13 = xr2a.y ^ wq3.y;
        unsigned int t14 = xr2b.x ^ wq3.z, t15 = xr2b.y ^ wq3.w;
        unsigned int t16 = xr2c.x ^ wq4.x, t17 = xr2c.y ^ wq4.y;

        // level-1: 6 CSAs
        unsigned int s0, s1, s2, s3, s4, s5, c0_, c1_, c2_, c3_, c4_, c5_;
        CSA(s0, c0_, t0, t1, t2);
        CSA(s1, c1_, t3, t4, t5);
        CSA(s2, c2_, t6, t7, t8);
        CSA(s3, c3_, t9, t10, t11);
        CSA(s4, c4_, t12, t13, t14);
        CSA(s5, c5_, t15, t16, t17);
        // level-2 sums: u@1 + d@2
        unsigned int u0 = s0 ^ s1 ^ s2;
        unsigned int u1 = s3 ^ s4 ^ s5;
        unsigned int d0 = MAJ(s0, s1, s2);
        unsigned int d1 = MAJ(s3, s4, s5);
        // level-2 carries: compress c0,c1,c2 -> v0@2 + e0@4  (k=9 balance)
        unsigned int v0, e0;
        CSA(v0, e0, c0_, c1_, c2_);

        int pu = __popc(u0) + __popc(u1);                      // @1
        int p2 = (__popc(v0) + __popc(c3_)) + (__popc(c4_) + __popc(c5_)) +
                 (__popc(d0) + __popc(d1));                    // @2
        int p4 = __popc(e0);                                   // @4
        int K = (int)0x4B000000 + pu + 2 * p2 + 4 * p4;
        float fS = __int_as_float(K) - 8388608.0f;

        int co = g * 32 + c;
        float v = fmaf(-2.0f, fS, c0v[co]);
        op[(size_t)c * (HDIM * WDIM)] = fmaf(fmaxf(v, 0.0f), sSC[co], sSH[co]);
    }
}

// ---------------------------------------------------------------------------
extern "C" void kernel_launch(void* const* d_in, const int* in_sizes, int n_in,
                              void* d_out, int out_size) {
    const float* x     = (const float*)d_in[0];
    const float* w     = (const float*)d_in[1];
    const float* b     = (const float*)d_in[2];
    const float* gamma = (const float*)d_in[3];
    const float* beta  = (const float*)d_in[4];
    const float* mean  = (const float*)d_in[5];
    const float* var   = (const float*)d_in[6];
    float* out = (float*)d_out;

    dim3 gp(WDIM / 64, HDIM, N_IMG + 1);   // z=16 slice carries binw
    k_prep<<<gp, 256>>>(x, w, b, gamma, beta, mean, var);

    dim3 gm(1, HDIM, N_IMG);
    k_main<<<gm, 512>>>(out);
}

// round 17
// speedup vs baseline: 1.0515x; 1.0515x over previous
#include <cuda_runtime.h>
#include <cstdint>

// ---------------------------------------------------------------------------
// BinConv(3x3,pad1)+bias+ReLU+eval-BN via bit-packed XNOR + CSA-popcount.
//   conv = C0 - 2*S,  S = sum_{18 words} popc(xbits ^ wbits)
//   k=8 CSA tree (measured optimum: R12/R15 vs R8 k=9-deep and R16 k=9-wide):
//   18 XOR -> 6 L1 CSAs -> sums {u0,u1}@1 + {d0,d1}@2, carries c0..c5@2
//   popc'd directly. float(S) via 2^23 magic number (no I2F).
// 2-kernel DAG: k_prep (binx all imgs + binw fused as grid-z slice) -> k_main.
// No stream overlap (R9/R13/R14: net-negative vs the alu-saturated k_main).
// ---------------------------------------------------------------------------

#define N_IMG 16
#define HDIM 256
#define WDIM 256
#define HP 258
#define WP 258

// zero-initialized: padded borders stay 0
__device__ __align__(16) unsigned int g_xb[(size_t)N_IMG * HP * WP * 2];
__device__ __align__(16) unsigned int g_wb[64 * 20];   // [co][tap*2+word], pad 20
__device__ float g_C0p[3 * 64], g_ELp[3 * 64], g_ERp[3 * 64];
__device__ float g_scale[64], g_shift[64];

// ---------------------------------------------------------------------------
// Fused prep. grid (4,256,17), block 256.
//   z < 16            : binarize+pack x rows (image z)
//   z == 16, x==0,y<64: pack weights + fold constants (cout = blockIdx.y)
// ---------------------------------------------------------------------------
__global__ void k_prep(const float* __restrict__ x, const float* __restrict__ w,
                       const float* __restrict__ b, const float* __restrict__ gamma,
                       const float* __restrict__ beta, const float* __restrict__ mean,
                       const float* __restrict__ var) {
    const int tid = threadIdx.x;

    if (blockIdx.z < N_IMG) {
        // ---------------- binx ----------------
        __shared__ unsigned short s16[64][4];
        const int n = blockIdx.z, h = blockIdx.y, w0 = blockIdx.x * 64;
        const int ww_ = tid & 63, cb = tid >> 6;
        const float* xp =
            x + (((size_t)n * 64 + cb * 16) * HDIM + h) * WDIM + w0 + ww_;
        unsigned int m = 0;
#pragma unroll
        for (int ci = 0; ci < 16; ci++) {
            float v = xp[(size_t)ci * (HDIM * WDIM)];
            m |= (v >= 0.0f ? 1u : 0u) << ci;
        }
        s16[ww_][cb] = (unsigned short)m;
        __syncthreads();
        if (tid < 128) {
            int wq = tid >> 1, word = tid & 1;
            unsigned int v = (unsigned int)s16[wq][2 * word] |
                             ((unsigned int)s16[wq][2 * word + 1] << 16);
            g_xb[(((size_t)n * HP + h + 1) * WP + (w0 + 1 + wq)) * 2 + word] = v;
        }
        return;
    }

    // ---------------- binw (64 blocks: x==0, y<64) ----------------
    if (blockIdx.x != 0 || blockIdx.y >= 64 || tid >= 64) return;
    __shared__ unsigned int sw[18];
    const int co = blockIdx.y, c = tid;
    const int lane = c & 31, warp = c >> 5;
#pragma unroll
    for (int tap = 0; tap < 9; tap++) {
        float wv = w[((size_t)co * 64 + c) * 9 + tap];
        unsigned int bal = __ballot_sync(0xffffffffu, wv >= 0.0f);
        if (lane == 0) sw[tap * 2 + warp] = bal;
    }
    __syncthreads();
    if (c < 18) g_wb[co * 20 + c] = sw[c];
    if (c == 0) {
        int tp[9];
        for (int t = 0; t < 9; t++)
            tp[t] = __popc(sw[t * 2]) + __popc(sw[t * 2 + 1]);
        float corr[3][3];
        for (int hp = 0; hp < 3; hp++)
            for (int lr = 0; lr < 3; lr++) {
                float s = 0.0f;
                for (int dy = 0; dy < 3; dy++)
                    for (int dx = 0; dx < 3; dx++) {
                        bool cut = (hp == 1 && dy == 0) || (hp == 2 && dy == 2) ||
                                   (lr == 1 && dx == 0) || (lr == 2 && dx == 2);
                        if (cut) s += 64.0f - 2.0f * (float)tp[dy * 3 + dx];
                    }
                corr[hp][lr] = s;
            }
        float bias = b[co];
        for (int hp = 0; hp < 3; hp++) {
            g_C0p[hp * 64 + co] = bias + 576.0f - corr[hp][0];
            g_ELp[hp * 64 + co] = corr[hp][0] - corr[hp][1];
            g_ERp[hp * 64 + co] = corr[hp][0] - corr[hp][2];
        }
        float inv = gamma[co] * rsqrtf(var[co] + 1e-5f);
        g_scale[co] = inv;
        g_shift[co] = beta[co] - mean[co] * inv;
    }
}

// ---------------------------------------------------------------------------
// Main: XNOR + CSA-popcount. CTA = 1 row (256 px) x 64 couts, 512 threads.
// thread = 1 px x 32 couts. grid (1,256,16).
// ---------------------------------------------------------------------------
#define CSA(s, cy, a, b, c)                          \
    {                                                \
        unsigned int _a = (a), _b = (b), _c = (c);   \
        (s) = _a ^ _b ^ _c;                          \
        (cy) = (_a & _b) | (_a & _c) | (_b & _c);    \
    }
#define MAJ(a, b, c) (((a) & (b)) | ((a) & (c)) | ((b) & (c)))

__global__ void __launch_bounds__(512, 2) k_main(float* __restrict__ out) {
    __shared__ uint2 s_x[3][260];
    __shared__ __align__(16) unsigned int s_w[64 * 20];
    __shared__ float sC0I[64], sC0L[64], sC0R[64], sSC[64], sSH[64];

    const int tid = threadIdx.x;
    const int n = blockIdx.z, h = blockIdx.y;
    const int hp = (h == 0) ? 1 : ((h == HDIM - 1) ? 2 : 0);

    {
        const uint2* xg = (const uint2*)g_xb + ((size_t)n * HP + h) * WP;
        for (int t = tid; t < 774; t += 512) {
            int dy = t / 258, i = t - dy * 258;
            s_x[dy][i] = xg[(size_t)dy * WP + i];
        }
    }
    // weights: 1280 u32 = 320 uint4, vectorized preload
    if (tid < 320)
        ((uint4*)s_w)[tid] = ((const uint4*)g_wb)[tid];
    if (tid < 64) {
        float c0 = g_C0p[hp * 64 + tid];
        sC0I[tid] = c0;
        sC0L[tid] = c0 + g_ELp[hp * 64 + tid];
        sC0R[tid] = c0 + g_ERp[hp * 64 + tid];
        sSC[tid] = g_scale[tid];
        sSH[tid] = g_shift[tid];
    }
    __syncthreads();

    const int px = tid & 255, g = tid >> 8;

    uint2 xr0a = s_x[0][px], xr0b = s_x[0][px + 1], xr0c = s_x[0][px + 2];
    uint2 xr1a = s_x[1][px], xr1b = s_x[1][px + 1], xr1c = s_x[1][px + 2];
    uint2 xr2a = s_x[2][px], xr2b = s_x[2][px + 1], xr2c = s_x[2][px + 2];

    const float* c0v = (px == 0) ? sC0L : ((px == 255) ? sC0R : sC0I);
    const unsigned int* wb = s_w + g * 32 * 20;
    float* op = out + (((size_t)n * 64 + g * 32) * HDIM + h) * WDIM + px;

#pragma unroll 4
    for (int c = 0; c < 32; c++) {
        const uint4* w4 = (const uint4*)(wb + c * 20);
        uint4 wq0 = w4[0], wq1 = w4[1], wq2 = w4[2], wq3 = w4[3];
        uint2 wq4 = *(const uint2*)(w4 + 4);
        unsigned int t0 = xr0a.x ^ wq0.x, t1 = xr0a.y ^ wq0.y;
        unsigned int t2 = xr0b.x ^ wq0.z, t3 = xr0b.y ^ wq0.w;
        unsigned int t4 = xr0c.x ^ wq1.x, t5 = xr0c.y ^ wq1.y;
        unsigned int t6 = xr1a.x ^ wq1.z, t7 = xr1a.y ^ wq1.w;
        unsigned int t8 = xr1b.x ^ wq2.x, t9 = xr1b.y ^ wq2.y;
        unsigned int t10 = xr1c.x ^ wq2.z, t11 = xr1c.y ^ wq2.w;
        unsigned int t12 = xr2a.x ^ wq3.x, t13 = xr2a.y ^ wq3.y;
        unsigned int t14 = xr2b.x ^ wq3.z, t15 = xr2b.y ^ wq3.w;
        unsigned int t16 = xr2c.x ^ wq4.x, t17 = xr2c.y ^ wq4.y;

        // level-1: 6 CSAs
        unsigned int s0, s1, s2, s3, s4, s5, c0_, c1_, c2_, c3_, c4_, c5_;
        CSA(s0, c0_, t0, t1, t2);
        CSA(s1, c1_, t3, t4, t5);
        CSA(s2, c2_, t6, t7, t8);
        CSA(s3, c3_, t9, t10, t11);
        CSA(s4, c4_, t12, t13, t14);
        CSA(s5, c5_, t15, t16, t17);
        // level-2 on sums only (k=8 optimum): u@1 + d@2; carries popc'd direct
        unsigned int u0 = s0 ^ s1 ^ s2;
        unsigned int u1 = s3 ^ s4 ^ s5;
        unsigned int d0 = MAJ(s0, s1, s2);
        unsigned int d1 = MAJ(s3, s4, s5);

        int pu = __popc(u0) + __popc(u1);
        int pcA = __popc(c0_) + __popc(c1_) + __popc(c2_);
        int pcB = __popc(c3_) + __popc(c4_) + __popc(c5_);
        int pd = __popc(d0) + __popc(d1);
        int K = (int)0x4B000000 + pu + 2 * (pcA + pcB + pd);
        float fS = __int_as_float(K) - 8388608.0f;

        int co = g * 32 + c;
        float v = fmaf(-2.0f, fS, c0v[co]);
        op[(size_t)c * (HDIM * WDIM)] = fmaf(fmaxf(v, 0.0f), sSC[co], sSH[co]);
    }
}

// ---------------------------------------------------------------------------
extern "C" void kernel_launch(void* const* d_in, const int* in_sizes, int n_in,
                              void* d_out, int out_size) {
    const float* x     = (const float*)d_in[0];
    const float* w     = (const float*)d_in[1];
    const float* b     = (const float*)d_in[2];
    const float* gamma = (const float*)d_in[3];
    const float* beta  = (const float*)d_in[4];
    const float* mean  = (const float*)d_in[5];
    const float* var   = (const float*)d_in[6];
    float* out = (float*)d_out;

    dim3 gp(WDIM / 64, HDIM, N_IMG + 1);   // z=16 slice carries binw
    k_prep<<<gp, 256>>>(x, w, b, gamma, beta, mean, var);

    dim3 gm(1, HDIM, N_IMG);
    k_main<<<gm, 512>>>(out);
}